// round 9
// baseline (speedup 1.0000x reference)
#include <cuda_runtime.h>

// TT-linear, R8: occupancy doubled at constant smem by parallelizing the
// pair-plane (pp) dimension across warps instead of serializing it.
// 512 threads = 2 super-groups x 256; within a super-group, warps 0-3 own
// pp0 and warps 4-7 own pp1 of the same row & pass. Same T1/T2 buffers as R7.
// x LDG for pass p+1 is prefetched under pass p's P2 compute.
//
// y[b,n1n2n3] = sum x[b,m1,m2,m3] c0[m1,n1,r1] c1[r1,m2,n2,r2] c2[r2,m3,n3] + bias
// B=4096, modes 16, ranks 8. 152 CTAs x 512 thr.

typedef unsigned long long u64;

__device__ __forceinline__ u64 pk2(float lo, float hi) {
    u64 d;
    asm("mov.b64 %0, {%1, %2};"
        : "=l"(d) : "r"(__float_as_uint(lo)), "r"(__float_as_uint(hi)));
    return d;
}
__device__ __forceinline__ float2 upk2(u64 v) {
    unsigned lo, hi;
    asm("mov.b64 {%0, %1}, %2;" : "=r"(lo), "=r"(hi) : "l"(v));
    return make_float2(__uint_as_float(lo), __uint_as_float(hi));
}
__device__ __forceinline__ u64 ffma2(u64 a, u64 b, u64 c) {
    u64 d;
    asm("fma.rn.f32x2 %0, %1, %2, %3;" : "=l"(d) : "l"(a), "l"(b), "l"(c));
    return d;
}
__device__ __forceinline__ void barg(int id) {
    asm volatile("bar.sync %0, 256;" :: "r"(id) : "memory");
}

__global__ __launch_bounds__(512, 1)
void tt_linear_kernel(const float* __restrict__ xg,
                      const float* __restrict__ c0g,
                      const float* __restrict__ c1g,
                      const float* __restrict__ c2g,
                      const float* __restrict__ biasg,
                      float* __restrict__ outg)
{
    extern __shared__ float smem[];
    // cores (shared by both super-groups)
    float* c0s = smem;            // 2048  : [m1*128 + n1*8 + r1]
    float* c1s = smem + 2048;     // 16384 : [(r1*16+m2)*128 + n2*8 + r2]
    float* c2s = smem + 18432;    // 2048  : [mpg*256 + (n3*8+r2)*2 + plane]
    const int tid = threadIdx.x;
    const int g  = tid >> 8;      // super-group (row) 0/1
    const int u  = tid & 255;     // thread within super-group
    const int pc = u >> 7;        // pair-plane owned by this warp-half
    const int tc = u & 127;       // column thread within pp
    // per-sg: xs 2*520, T1 2*4096, T2 2*4096 = 17424 floats
    float* xs  = smem + 20480 + g * 17424;  // [pp*520 + (m1*16+m2)*2 + plane]
    float* T1s = xs + 1040;                 // [pp*4096 + (m2*128 + col)*2 + plane], col = r1*16+n1
    float* T2t = T1s + 8192;                // [pp*4096 + (r2*256 + n1*16 + n2)*2 + plane]

    // ---- stage cores (once per CTA) ----
    for (int i = tid; i < 2048; i += 512) c0s[i] = c0g[i];
    for (int i = tid; i < 16384; i += 512) c1s[i] = c1g[i];
    for (int i = tid; i < 2048; i += 512) {
        int mpg = i >> 8;
        int rem = i & 255;
        int plane = rem & 1;
        int idx = rem >> 1;            // n3*8 + r2
        int n3 = idx >> 3, r2 = idx & 7;
        c2s[i] = c2g[r2 * 256 + (2 * mpg + plane) * 16 + n3];
    }
    __syncthreads();

    // c0 column: T1 col = tc = r1*16 + n1  ->  c0[m1][n1*8 + r1]
    float c0col[16];
    {
        const int n1t = tc & 15, r1t = tc >> 4;
#pragma unroll
        for (int m1 = 0; m1 < 16; ++m1)
            c0col[m1] = c0s[m1 * 128 + n1t * 8 + r1t];
    }

    const int wq = (u >> 5) & 3;  // warp within pp -> n1 set {4wq..4wq+3}
    const int j  = u & 31;        // lane -> d set {4j..4j+3}
    const int mybar = g + 1;

    const int strideR = gridDim.x * 2;
    const int iters = (4096 + strideR - 1) / strideR;   // uniform (barrier-safe)
    const int bid2 = blockIdx.x * 2 + g;

    // flat-pass x address: pass p -> (iter p>>2, qp p&3)
    auto xfetch = [&](int p) -> float4 {
        int r = bid2 + (p >> 2) * strideR;
        if (r > 4095) r = 4095;
        const float4* xr4 = (const float4*)(xg + (size_t)r * 4096);
        return xr4[u * 4 + (p & 3)];
    };

    float4 xv = xfetch(0);   // prefetch pass 0

    for (int it = 0; it < iters; ++it) {
        const int row = bid2 + it * strideR;
        const bool active = row < 4096;

        float acc[16];
#pragma unroll
        for (int q = 0; q < 16; ++q) acc[q] = 0.0f;

#pragma unroll 1
        for (int qp = 0; qp < 4; ++qp) {    // pass: planes 4qp..4qp+3
            // ---- store prefetched x, pair-interleaved into xs ----
            *(float2*)(xs + u * 2)       = make_float2(xv.x, xv.y);   // pp0
            *(float2*)(xs + 520 + u * 2) = make_float2(xv.z, xv.w);   // pp1
            barg(mybar);

            // ===== Phase 1: T1 pairs for own pp (col = tc) =====
            {
                u64 t1p[16];
#pragma unroll
                for (int m2 = 0; m2 < 16; ++m2) t1p[m2] = 0ULL;
                const float* xp = xs + pc * 520;
#pragma unroll 4
                for (int m1 = 0; m1 < 16; ++m1) {
                    const u64 cvp = pk2(c0col[m1], c0col[m1]);
                    const ulonglong2* qv = (const ulonglong2*)(xp + m1 * 32);
#pragma unroll
                    for (int qq = 0; qq < 8; ++qq) {
                        ulonglong2 v = qv[qq];          // uniform broadcast LDS.128
                        t1p[2 * qq]     = ffma2(v.x, cvp, t1p[2 * qq]);
                        t1p[2 * qq + 1] = ffma2(v.y, cvp, t1p[2 * qq + 1]);
                    }
                }
                float* T1p = T1s + pc * 4096;
#pragma unroll
                for (int m2 = 0; m2 < 16; ++m2)
                    *(u64*)(T1p + (m2 * 128 + tc) * 2) = t1p[m2];
            }
            barg(mybar);

            // prefetch x for next pass (hidden under P2 compute)
            xv = xfetch(it * 4 + qp + 1);

            // ===== Phase 2: own pp; thread = 4 n1 x 4 d =====
            // q2[a*4+c]: n1 = 4wq+a, d = 4j+c, value = packed (planeA, planeB)
            u64 q2[16];
#pragma unroll
            for (int q = 0; q < 16; ++q) q2[q] = 0ULL;

            {
                const float* bbase = c1s + 4 * j;                 // + k*128
                const float* abase = T1s + pc * 4096 + (4 * wq) * 2;
#pragma unroll 1
                for (int m2 = 0; m2 < 16; ++m2) {
                    const float* bm = bbase + m2 * 128;           // + r1*2048
                    const float* am = abase + m2 * 256;           // + r1*32
#pragma unroll
                    for (int r1 = 0; r1 < 8; ++r1) {
                        float4 bf = *(const float4*)(bm + r1 * 2048);  // coalesced LDS.128
                        u64 b0 = pk2(bf.x, bf.x);
                        u64 b1 = pk2(bf.y, bf.y);
                        u64 b2 = pk2(bf.z, bf.z);
                        u64 b3 = pk2(bf.w, bf.w);
                        const float* ap = am + r1 * 32;
                        ulonglong2 a01 = *(const ulonglong2*)(ap);       // warp-uniform
                        ulonglong2 a23 = *(const ulonglong2*)(ap + 4);   // warp-uniform
                        q2[0]  = ffma2(a01.x, b0, q2[0]);
                        q2[1]  = ffma2(a01.x, b1, q2[1]);
                        q2[2]  = ffma2(a01.x, b2, q2[2]);
                        q2[3]  = ffma2(a01.x, b3, q2[3]);
                        q2[4]  = ffma2(a01.y, b0, q2[4]);
                        q2[5]  = ffma2(a01.y, b1, q2[5]);
                        q2[6]  = ffma2(a01.y, b2, q2[6]);
                        q2[7]  = ffma2(a01.y, b3, q2[7]);
                        q2[8]  = ffma2(a23.x, b0, q2[8]);
                        q2[9]  = ffma2(a23.x, b1, q2[9]);
                        q2[10] = ffma2(a23.x, b2, q2[10]);
                        q2[11] = ffma2(a23.x, b3, q2[11]);
                        q2[12] = ffma2(a23.y, b0, q2[12]);
                        q2[13] = ffma2(a23.y, b1, q2[13]);
                        q2[14] = ffma2(a23.y, b2, q2[14]);
                        q2[15] = ffma2(a23.y, b3, q2[15]);
                    }
                }
            }
            // transposed store into own pp's T2 plane
            {
                float* T2p = T2t + pc * 4096;
#pragma unroll
                for (int a = 0; a < 4; ++a) {
                    const int n1 = 4 * wq + a;
#pragma unroll
                    for (int c = 0; c < 4; ++c) {
                        const int d = 4 * j + c;
                        const int addr = ((d & 7) * 256 + n1 * 16 + (d >> 3)) * 2;
                        *(u64*)(T2p + addr) = q2[a * 4 + c];
                    }
                }
            }
            barg(mybar);

            // ===== Phase 3: accumulate output; thread owns pos = u =====
            {
                u64 tv0[8], tv1[8];
#pragma unroll
                for (int r2 = 0; r2 < 8; ++r2) {
                    tv0[r2] = *(const u64*)(T2t + (r2 * 256 + u) * 2);          // pp0, coalesced
                    tv1[r2] = *(const u64*)(T2t + 4096 + (r2 * 256 + u) * 2);   // pp1, coalesced
                }
                const float* c2p0 = c2s + (2 * qp) * 256;
                const float* c2p1 = c2p0 + 256;
#pragma unroll
                for (int n3 = 0; n3 < 16; ++n3) {
                    u64 a0 = 0ULL, a1 = 0ULL;
#pragma unroll
                    for (int r2p = 0; r2p < 4; ++r2p) {
                        ulonglong2 cp0 = *(const ulonglong2*)
                            (c2p0 + (n3 * 8 + 2 * r2p) * 2);   // uniform broadcast
                        ulonglong2 cp1 = *(const ulonglong2*)
                            (c2p1 + (n3 * 8 + 2 * r2p) * 2);
                        a0 = ffma2(tv0[2 * r2p],     cp0.x, a0);
                        a0 = ffma2(tv0[2 * r2p + 1], cp0.y, a0);
                        a1 = ffma2(tv1[2 * r2p],     cp1.x, a1);
                        a1 = ffma2(tv1[2 * r2p + 1], cp1.y, a1);
                    }
                    float2 f0 = upk2(a0), f1 = upk2(a1);
                    acc[n3] += (f0.x + f0.y) + (f1.x + f1.y);
                }
            }
            // T2 reads here vs next pass's P2 writes: ordered by next pass's
            // two barriers. xs overwrite at next pass top: P1 readers finished
            // two barriers ago.
        }

        // ---- add bias, store 16 outputs (pos = u) ----
        if (active) {
            float* og = outg + (size_t)row * 4096 + u * 16;
            const float* bp = biasg + u * 16;
#pragma unroll
            for (int q = 0; q < 4; ++q) {
                float4 b4 = *(const float4*)(bp + 4 * q);
                float4 v;
                v.x = acc[4 * q + 0] + b4.x;
                v.y = acc[4 * q + 1] + b4.y;
                v.z = acc[4 * q + 2] + b4.z;
                v.w = acc[4 * q + 3] + b4.w;
                *(float4*)(og + 4 * q) = v;
            }
        }
    }
}

extern "C" void kernel_launch(void* const* d_in, const int* in_sizes, int n_in,
                              void* d_out, int out_size)
{
    const float* x    = (const float*)d_in[0];
    const float* c0   = (const float*)d_in[1];
    const float* c1   = (const float*)d_in[2];
    const float* c2   = (const float*)d_in[3];
    const float* bias = (const float*)d_in[4];
    float* out = (float*)d_out;

    // 20480 (cores) + 2 * 17424 (xs + T1 + T2 per super-group) = 55328 floats
    const int smem_bytes = 55328 * (int)sizeof(float);   // 221312 B
    cudaFuncSetAttribute(tt_linear_kernel,
                         cudaFuncAttributeMaxDynamicSharedMemorySize, smem_bytes);

    tt_linear_kernel<<<152, 512, smem_bytes>>>(x, c0, c1, c2, bias, out);
}

// round 11
// speedup vs baseline: 1.0029x; 1.0029x over previous
#include <cuda_runtime.h>
#include <cuda_bf16.h>
#include <cstdint>

// ============================================================================
// TT-linear via densified W + split-bf16 tcgen05 GEMM (cg2, 256x256 tiles).
//   y = x @ W + bias,  W[m][n] = sum_{r1,r2} c0[m1,n1,r1] c1[r1,m2,n2,r2] c2[r2,m3,n3]
// Split: y = A_hi B_hi + A_lo B_hi + A_hi B_lo (bf16 hi/lo, fp32 accum).
// All tcgen05 code is guarded by the sm_103a feature macro so the plain
// compute_103 pass compiles a correct SIMT fallback (insurance only — the
// runtime picks the exact sm_103a SASS).
// ============================================================================

#if defined(__CUDA_ARCH_FEAT_SM103_ALL) || defined(__CUDA_ARCH_FEAT_SM100_ALL) || defined(__CUDA_ARCH_FEAT_SM101_ALL)
#define HAS_TCGEN05 1
#endif

typedef unsigned long long u64;

// -------- device scratch (allocation-free rule: __device__ globals) --------
__device__ __nv_bfloat16 g_Ahi[4096u * 4096u];
__device__ __nv_bfloat16 g_Alo[4096u * 4096u];
__device__ __nv_bfloat16 g_Bhi[4096u * 4096u];   // K-major: [n][m]
__device__ __nv_bfloat16 g_Blo[4096u * 4096u];   // K-major: [n][m]

// -------- helpers legal on any sm_90+ target --------
__device__ __forceinline__ uint32_t smem_u32(const void* p) {
    uint32_t a;
    asm("{ .reg .u64 t; cvta.to.shared.u64 t, %1; cvt.u32.u64 %0, t; }"
        : "=r"(a) : "l"(p));
    return a;
}
__device__ __forceinline__ uint32_t elect_one() {
    uint32_t pred;
    asm volatile(
        "{\n\t.reg .pred p;\n\t"
        "elect.sync _|p, 0xFFFFFFFF;\n\t"
        "selp.b32 %0, 1, 0, p;\n\t}"
        : "=r"(pred));
    return pred;
}
__device__ __forceinline__ uint32_t cta_rank() {
    uint32_t r; asm("mov.u32 %0, %%cluster_ctarank;" : "=r"(r)); return r;
}
__device__ __forceinline__ void cpasync16(uint32_t dst, const void* src) {
    asm volatile("cp.async.cg.shared.global [%0], [%1], 16;"
                 :: "r"(dst), "l"(src) : "memory");
}
__device__ __forceinline__ void cp_commit() {
    asm volatile("cp.async.commit_group;" ::: "memory");
}
__device__ __forceinline__ void cp_wait2() {
    asm volatile("cp.async.wait_group 2;" ::: "memory");
}

#define MBARRIER_INIT(addr, cnt) \
    asm volatile("mbarrier.init.shared.b64 [%0], %1;" \
                 :: "r"((uint32_t)(addr)), "r"((uint32_t)(cnt)) : "memory")

#define MBAR_ARRIVE_CLU(addr, rk) \
    asm volatile("{\n\t.reg .b32 ra;\n\t" \
                 "mapa.shared::cluster.u32 ra, %0, %1;\n\t" \
                 "mbarrier.arrive.shared::cluster.b64 _, [ra];\n\t}" \
                 :: "r"((uint32_t)(addr)), "r"((uint32_t)(rk)) : "memory")

#define MBAR_WAIT_PAR_CLU(addr, par) do {                                   \
    uint32_t _m = (uint32_t)(addr);                                         \
    uint32_t _p = (uint32_t)(par);                                          \
    asm volatile(                                                           \
        "{\n\t.reg .pred P;\n\t"                                            \
        "WL_%=:\n\t"                                                        \
        "mbarrier.try_wait.parity.acquire.cluster.shared::cta.b64 P, [%0], %1, 0x989680;\n\t" \
        "@P bra.uni WD_%=;\n\t"                                             \
        "bra.uni WL_%=;\n\t"                                                \
        "WD_%=:\n\t}"                                                       \
        :: "r"(_m), "r"(_p) : "memory");                                    \
} while (0)

#define FENCE_PROXY_ASYNC() asm volatile("fence.proxy.async;" ::: "memory")

__device__ __forceinline__ uint32_t sw128(uint32_t off) {
    return off ^ ((off >> 3) & 0x70);
}

#ifdef HAS_TCGEN05
// -------- tcgen05 constructs (sm_103a-only; must stay inside the guard) ----
#define TCGEN05_ALLOC_CG2(sa, n) \
    asm volatile("tcgen05.alloc.cta_group::2.sync.aligned.shared::cta.b32 [%0], %1;" \
                 :: "r"((uint32_t)(sa)), "r"((uint32_t)(n)) : "memory")
#define TCGEN05_DEALLOC_CG2(tm, n) \
    asm volatile("tcgen05.dealloc.cta_group::2.sync.aligned.b32 %0, %1;" \
                 :: "r"(tm), "r"((uint32_t)(n)))
#define TCGEN05_RELINQ_CG2() \
    asm volatile("tcgen05.relinquish_alloc_permit.cta_group::2.sync.aligned;")
#define TCGEN05_COMMIT_MC_CG2(mbar, mask) \
    asm volatile("tcgen05.commit.cta_group::2.mbarrier::arrive::one.shared::cluster.multicast::cluster.b64 [%0], %1;" \
                 :: "r"((uint32_t)(mbar)), "h"((uint16_t)(mask)) : "memory")
#define TCGEN05_FENCE_AFTER() \
    asm volatile("tcgen05.fence::after_thread_sync;" ::: "memory")
#define TCGEN05_FENCE_BEFORE() \
    asm volatile("tcgen05.fence::before_thread_sync;" ::: "memory")
#define TCGEN05_WAIT_LD() \
    asm volatile("tcgen05.wait::ld.sync.aligned;" ::: "memory")

#define TCGEN05_LD_X32(r, ta) \
    asm volatile( \
        "tcgen05.ld.sync.aligned.32x32b.x32.b32 " \
        "{%0, %1, %2, %3, %4, %5, %6, %7, " \
        " %8, %9, %10, %11, %12, %13, %14, %15, " \
        " %16, %17, %18, %19, %20, %21, %22, %23, " \
        " %24, %25, %26, %27, %28, %29, %30, %31}, [%32];" \
        : "=r"((r)[0]),  "=r"((r)[1]),  "=r"((r)[2]),  "=r"((r)[3]), \
          "=r"((r)[4]),  "=r"((r)[5]),  "=r"((r)[6]),  "=r"((r)[7]), \
          "=r"((r)[8]),  "=r"((r)[9]),  "=r"((r)[10]), "=r"((r)[11]), \
          "=r"((r)[12]), "=r"((r)[13]), "=r"((r)[14]), "=r"((r)[15]), \
          "=r"((r)[16]), "=r"((r)[17]), "=r"((r)[18]), "=r"((r)[19]), \
          "=r"((r)[20]), "=r"((r)[21]), "=r"((r)[22]), "=r"((r)[23]), \
          "=r"((r)[24]), "=r"((r)[25]), "=r"((r)[26]), "=r"((r)[27]), \
          "=r"((r)[28]), "=r"((r)[29]), "=r"((r)[30]), "=r"((r)[31]) \
        : "r"(ta))

__device__ __forceinline__ void mma_f16_ss_cg2(
    uint32_t d_tmem, u64 a_desc, u64 b_desc, uint32_t idesc, bool en)
{
    uint32_t e = en ? 1u : 0u;
    asm volatile(
        "{\n\t.reg .pred p;\n\t"
        "setp.ne.u32 p, %6, 0;\n\t"
        "tcgen05.mma.cta_group::2.kind::f16 [%0], %1, %2, %3, "
        "{%4, %4, %4, %4, %4, %4, %4, %4}, p;\n\t}"
        :: "r"(d_tmem), "l"(a_desc), "l"(b_desc), "r"(idesc),
           "r"(0u), "r"(0u), "r"(e)
        : "memory");
}

static constexpr u64 SMEM_DESC_SW128 =
    (u64(2) << 61) | (u64(1) << 46) | (u64(64) << 32) | (u64(1) << 16);
__device__ __forceinline__ u64 mk_desc(uint32_t a) {
    return SMEM_DESC_SW128 | ((u64)(a >> 4) & 0x3FFF);
}
#endif  // HAS_TCGEN05

// ============================================================================
// Kernel 1: split x into bf16 hi/lo
// ============================================================================
__global__ __launch_bounds__(256) void k_split_x(const float* __restrict__ xg)
{
    const float4* x4 = (const float4*)xg;
    uint32_t* ahi = (uint32_t*)g_Ahi;
    uint32_t* alo = (uint32_t*)g_Alo;
    int stride = gridDim.x * blockDim.x;
    for (int q = blockIdx.x * blockDim.x + threadIdx.x; q < 4194304; q += stride) {
        float4 v = x4[q];
        __nv_bfloat16 h0 = __float2bfloat16_rn(v.x);
        __nv_bfloat16 h1 = __float2bfloat16_rn(v.y);
        __nv_bfloat16 h2 = __float2bfloat16_rn(v.z);
        __nv_bfloat16 h3 = __float2bfloat16_rn(v.w);
        __nv_bfloat16 l0 = __float2bfloat16_rn(v.x - __bfloat162float(h0));
        __nv_bfloat16 l1 = __float2bfloat16_rn(v.y - __bfloat162float(h1));
        __nv_bfloat16 l2 = __float2bfloat16_rn(v.z - __bfloat162float(h2));
        __nv_bfloat16 l3 = __float2bfloat16_rn(v.w - __bfloat162float(h3));
        __nv_bfloat162 hh0 = {h0, h1}, hh1 = {h2, h3};
        __nv_bfloat162 ll0 = {l0, l1}, ll1 = {l2, l3};
        ahi[2 * q]     = *(uint32_t*)&hh0;
        ahi[2 * q + 1] = *(uint32_t*)&hh1;
        alo[2 * q]     = *(uint32_t*)&ll0;
        alo[2 * q + 1] = *(uint32_t*)&ll1;
    }
}

// ============================================================================
// Kernel 2: densify W^T (K-major [n][m]) into bf16 hi/lo
// ============================================================================
__global__ __launch_bounds__(256) void k_densify(const float* __restrict__ c0g,
                                                 const float* __restrict__ c1g,
                                                 const float* __restrict__ c2g)
{
    __shared__ float sE[2048];
    __shared__ float sc2[2048];
    const int tid = threadIdx.x;
    const int m1 = blockIdx.x >> 4;
    const int m2 = blockIdx.x & 15;
    const int n1 = tid >> 4, n2 = tid & 15;

    float c0r[8];
#pragma unroll
    for (int r1 = 0; r1 < 8; ++r1) c0r[r1] = c0g[m1 * 128 + n1 * 8 + r1];
#pragma unroll
    for (int r2 = 0; r2 < 8; ++r2) {
        float acc = 0.0f;
#pragma unroll
        for (int r1 = 0; r1 < 8; ++r1)
            acc += c0r[r1] * c1g[(r1 * 16 + m2) * 128 + n2 * 8 + r2];
        sE[tid * 8 + r2] = acc;
    }
    for (int i = tid; i < 2048; i += 256) sc2[i] = c2g[i];
    __syncthreads();

    float Er[8];
#pragma unroll
    for (int r2 = 0; r2 < 8; ++r2) Er[r2] = sE[tid * 8 + r2];

#pragma unroll 1
    for (int n3 = 0; n3 < 16; ++n3) {
        __nv_bfloat16 hi[16], lo[16];
#pragma unroll
        for (int m3 = 0; m3 < 16; ++m3) {
            float w = 0.0f;
#pragma unroll
            for (int r2 = 0; r2 < 8; ++r2)
                w += Er[r2] * sc2[r2 * 256 + m3 * 16 + n3];
            __nv_bfloat16 h = __float2bfloat16_rn(w);
            hi[m3] = h;
            lo[m3] = __float2bfloat16_rn(w - __bfloat162float(h));
        }
        const int n = n1 * 256 + n2 * 16 + n3;
        const size_t boff = (size_t)n * 4096 + m1 * 256 + m2 * 16;
        *(uint4*)(g_Bhi + boff)     = ((uint4*)hi)[0];
        *(uint4*)(g_Bhi + boff + 8) = ((uint4*)hi)[1];
        *(uint4*)(g_Blo + boff)     = ((uint4*)lo)[0];
        *(uint4*)(g_Blo + boff + 8) = ((uint4*)lo)[1];
    }
}

// ============================================================================
// Kernel 3: cg2 tcgen05 GEMM, 256x256 tiles, 3-term split-bf16, K=4096.
// (#else: correct SIMT fallback using hi+lo W — insurance for non-'a' passes)
// ============================================================================
static constexpr int KSTEPS = 64;
static constexpr uint32_t GIDESC =
    (1u << 4) | (1u << 7) | (1u << 10) | (32u << 17) | (16u << 24);

static constexpr int OFF_TMEM  = 0;
static constexpr int OFF_READY = 16;
static constexpr int OFF_DONE  = 48;
static constexpr int OFF_TILES = 1024;
static constexpr int GEMM_SMEM = 1024 + 3 * 65536;   // 197632 B

__global__ __launch_bounds__(256, 1) __cluster_dims__(2, 1, 1)
void k_gemm(const float* __restrict__ xg, const float* __restrict__ biasg,
            float* __restrict__ outg)
{
#ifdef HAS_TCGEN05
    extern __shared__ char smem[];
    const uint32_t sb = smem_u32(smem);
    const int tid = threadIdx.x;
    const int wid = tid >> 5;
    const int lane = tid & 31;
    const uint32_t rank = cta_rank();

    const int pair  = blockIdx.x >> 1;
    const int mtile = pair >> 4;
    const int ntile = pair & 15;
    const int m_base = mtile * 256 + (int)rank * 128;
    const int n_base = ntile * 256 + (int)rank * 128;

    if (tid == 0) {
#pragma unroll
        for (int s = 0; s < 3; ++s) {
            MBARRIER_INIT(sb + OFF_READY + s * 8, 2);
            MBARRIER_INIT(sb + OFF_DONE + s * 8, 1);
        }
    }
    if (wid == 0) TCGEN05_ALLOC_CG2(sb + OFF_TMEM, 256);
    __syncthreads();
    uint32_t tmem;
    asm volatile("ld.shared.b32 %0, [%1];" : "=r"(tmem) : "r"(sb + OFF_TMEM));

    asm volatile("barrier.cluster.arrive.aligned;" ::: "memory");
    asm volatile("barrier.cluster.wait.aligned;" ::: "memory");

    // ---------------- loader warps (1..7) ----------------
    if (wid > 0) {
        const int lt = tid - 32;   // 0..223
        auto issue = [&](int ks) {
            const int s = ks % 3;
            const uint32_t stage = sb + OFF_TILES + s * 65536;
            for (int c = lt; c < 4096; c += 224) {
                const int tile = c >> 10;
                const int idx  = c & 1023;
                const int row  = idx >> 3;
                const int c16  = idx & 7;
                const __nv_bfloat16* src;
                if (tile == 0)      src = g_Ahi + (size_t)(m_base + row) * 4096;
                else if (tile == 1) src = g_Alo + (size_t)(m_base + row) * 4096;
                else if (tile == 2) src = g_Bhi + (size_t)(n_base + row) * 4096;
                else                src = g_Blo + (size_t)(n_base + row) * 4096;
                src += ks * 64 + c16 * 8;
                const uint32_t dst = stage + tile * 16384 + sw128(row * 128 + c16 * 16);
                cpasync16(dst, src);
            }
            cp_commit();
        };
        issue(0); issue(1); issue(2);

        for (int ks = 0; ks < KSTEPS; ++ks) {
            const int s = ks % 3;
            const uint32_t par = (uint32_t)((ks / 3) & 1);
            cp_wait2();
            FENCE_PROXY_ASYNC();                            // publish this thread's smem writes to async proxy
            asm volatile("bar.sync 1, 224;" ::: "memory");  // all loaders done+fenced
            if (lt == 0)
                MBAR_ARRIVE_CLU(sb + OFF_READY + s * 8, 0); // arrive leader's ready[s]
            MBAR_WAIT_PAR_CLU(sb + OFF_DONE + s * 8, par);  // MMA(ks) done reading stage s
            if (ks + 3 < KSTEPS) issue(ks + 3);
            else cp_commit();                               // keep group accounting aligned
        }
    }
    // ---------------- MMA warp (leader CTA warp 0) ----------------
    else if (rank == 0) {
        for (int ks = 0; ks < KSTEPS; ++ks) {
            const int s = ks % 3;
            const uint32_t par = (uint32_t)((ks / 3) & 1);
            MBAR_WAIT_PAR_CLU(sb + OFF_READY + s * 8, par);
            if (elect_one()) {
                const uint32_t stage = sb + OFF_TILES + s * 65536;
                const u64 dAhi = mk_desc(stage);
                const u64 dAlo = mk_desc(stage + 16384);
                const u64 dBhi = mk_desc(stage + 32768);
                const u64 dBlo = mk_desc(stage + 49152);
#pragma unroll
                for (int k = 0; k < 4; ++k)
                    mma_f16_ss_cg2(tmem, dAhi + k * 2, dBhi + k * 2, GIDESC, !(ks == 0 && k == 0));
#pragma unroll
                for (int k = 0; k < 4; ++k)
                    mma_f16_ss_cg2(tmem, dAlo + k * 2, dBhi + k * 2, GIDESC, true);
#pragma unroll
                for (int k = 0; k < 4; ++k)
                    mma_f16_ss_cg2(tmem, dAhi + k * 2, dBlo + k * 2, GIDESC, true);
                TCGEN05_COMMIT_MC_CG2(sb + OFF_DONE + s * 8, 0x3);
            }
        }
    }

    __syncthreads();
    TCGEN05_FENCE_AFTER();

    // ---------------- epilogue: 128 lanes x 256 fp32 cols + bias -------------
    {
        const int sp = wid & 3;
        const int ch = wid >> 2;
        const int m_global = mtile * 256 + (int)rank * 128 + sp * 32 + lane;
        float* orow = outg + (size_t)m_global * 4096 + ntile * 256 + ch * 128;
        const float* brow = biasg + ntile * 256 + ch * 128;
        uint32_t r[32];
#pragma unroll 1
        for (int cb = 0; cb < 4; ++cb) {
            TCGEN05_LD_X32(r, tmem + ch * 128 + cb * 32);
            TCGEN05_WAIT_LD();
#pragma unroll
            for (int c = 0; c < 32; c += 4) {
                float4 b4 = *(const float4*)(brow + cb * 32 + c);
                float4 v;
                v.x = __uint_as_float(r[c + 0]) + b4.x;
                v.y = __uint_as_float(r[c + 1]) + b4.y;
                v.z = __uint_as_float(r[c + 2]) + b4.z;
                v.w = __uint_as_float(r[c + 3]) + b4.w;
                *(float4*)(orow + cb * 32 + c) = v;
            }
        }
        TCGEN05_FENCE_BEFORE();
    }

    __syncthreads();
    if (wid == 0) {
        TCGEN05_RELINQ_CG2();
        TCGEN05_DEALLOC_CG2(tmem, 256);
    }
    asm volatile("barrier.cluster.arrive.aligned;" ::: "memory");
    asm volatile("barrier.cluster.wait.aligned;" ::: "memory");
#else
    // -------- fallback: correct SIMT GEMM from hi+lo W (never the fast path) --
    const int T = blockIdx.x * 256 + threadIdx.x;   // 0..131071
    const int n  = T & 4095;
    const int mg = T >> 12;                          // 0..31 -> 128 rows each
    const __nv_bfloat16* bh = g_Bhi + (size_t)n * 4096;
    const __nv_bfloat16* bl = g_Blo + (size_t)n * 4096;
    const float bv = biasg[n];
    for (int mi = 0; mi < 128; ++mi) {
        const int m = mg * 128 + mi;
        const float* xr = xg + (size_t)m * 4096;
        float acc = 0.0f;
        for (int k = 0; k < 4096; ++k)
            acc += xr[k] * (__bfloat162float(bh[k]) + __bfloat162float(bl[k]));
        outg[(size_t)m * 4096 + n] = acc + bv;
    }
#endif
}

// ============================================================================
extern "C" void kernel_launch(void* const* d_in, const int* in_sizes, int n_in,
                              void* d_out, int out_size)
{
    const float* x    = (const float*)d_in[0];
    const float* c0   = (const float*)d_in[1];
    const float* c1   = (const float*)d_in[2];
    const float* c2   = (const float*)d_in[3];
    const float* bias = (const float*)d_in[4];
    float* out = (float*)d_out;

    k_split_x<<<2048, 256>>>(x);
    k_densify<<<256, 256>>>(c0, c1, c2);

    cudaFuncSetAttribute(k_gemm, cudaFuncAttributeMaxDynamicSharedMemorySize,
                         GEMM_SMEM);
    k_gemm<<<512, 256, GEMM_SMEM>>>(x, bias, out);
}

// round 12
// speedup vs baseline: 2.1008x; 2.0947x over previous
#include <cuda_runtime.h>
#include <cuda_fp16.h>
#include <cstdint>

// ============================================================================
// TT-linear via densified W + 2-term split-fp16 tcgen05 GEMM (cg2, 256x256).
//   y = x @ W + bias;  y ≈ (A_hi + A_lo) · B_hi   (fp16, fp32 accumulate)
//   A_hi/A_lo: fp16 hi/lo split of x (x to ~2^-22); B_hi = fp16(W^T) K-major.
//   Dropped x·W_lo term -> rel_err ~2.8e-4 (norm), threshold 1e-3.
// KB=128 per kstep, 2-stage double buffer, ready-arrive decoupled from
// done-wait so the MMA warp's next kstep is armed one step early.
// ============================================================================

#if defined(__CUDA_ARCH_FEAT_SM103_ALL) || defined(__CUDA_ARCH_FEAT_SM100_ALL) || defined(__CUDA_ARCH_FEAT_SM101_ALL)
#define HAS_TCGEN05 1
#endif

typedef unsigned long long u64;

// -------- device scratch --------
__device__ __half g_Ahi[4096u * 4096u];
__device__ __half g_Alo[4096u * 4096u];
__device__ __half g_Bhi[4096u * 4096u];   // K-major: [n][m]

// -------- arch-neutral helpers --------
__device__ __forceinline__ uint32_t smem_u32(const void* p) {
    uint32_t a;
    asm("{ .reg .u64 t; cvta.to.shared.u64 t, %1; cvt.u32.u64 %0, t; }"
        : "=r"(a) : "l"(p));
    return a;
}
__device__ __forceinline__ uint32_t elect_one() {
    uint32_t pred;
    asm volatile(
        "{\n\t.reg .pred p;\n\t"
        "elect.sync _|p, 0xFFFFFFFF;\n\t"
        "selp.b32 %0, 1, 0, p;\n\t}"
        : "=r"(pred));
    return pred;
}
__device__ __forceinline__ uint32_t cta_rank() {
    uint32_t r; asm("mov.u32 %0, %%cluster_ctarank;" : "=r"(r)); return r;
}
__device__ __forceinline__ void cpasync16(uint32_t dst, const void* src) {
    asm volatile("cp.async.cg.shared.global [%0], [%1], 16;"
                 :: "r"(dst), "l"(src) : "memory");
}
__device__ __forceinline__ void cp_commit() {
    asm volatile("cp.async.commit_group;" ::: "memory");
}
__device__ __forceinline__ void cp_wait0() {
    asm volatile("cp.async.wait_group 0;" ::: "memory");
}
__device__ __forceinline__ void cp_wait1() {
    asm volatile("cp.async.wait_group 1;" ::: "memory");
}

#define MBARRIER_INIT(addr, cnt) \
    asm volatile("mbarrier.init.shared.b64 [%0], %1;" \
                 :: "r"((uint32_t)(addr)), "r"((uint32_t)(cnt)) : "memory")

#define MBAR_ARRIVE_CLU(addr, rk) \
    asm volatile("{\n\t.reg .b32 ra;\n\t" \
                 "mapa.shared::cluster.u32 ra, %0, %1;\n\t" \
                 "mbarrier.arrive.shared::cluster.b64 _, [ra];\n\t}" \
                 :: "r"((uint32_t)(addr)), "r"((uint32_t)(rk)) : "memory")

#define MBAR_WAIT_PAR_CLU(addr, par) do {                                   \
    uint32_t _m = (uint32_t)(addr);                                         \
    uint32_t _p = (uint32_t)(par);                                          \
    asm volatile(                                                           \
        "{\n\t.reg .pred P;\n\t"                                            \
        "WL_%=:\n\t"                                                        \
        "mbarrier.try_wait.parity.acquire.cluster.shared::cta.b64 P, [%0], %1, 0x989680;\n\t" \
        "@P bra.uni WD_%=;\n\t"                                             \
        "bra.uni WL_%=;\n\t"                                                \
        "WD_%=:\n\t}"                                                       \
        :: "r"(_m), "r"(_p) : "memory");                                    \
} while (0)

#define FENCE_PROXY_ASYNC() asm volatile("fence.proxy.async;" ::: "memory")

__device__ __forceinline__ uint32_t sw128(uint32_t off) {
    return off ^ ((off >> 3) & 0x70);
}

#ifdef HAS_TCGEN05
#define TCGEN05_ALLOC_CG2(sa, n) \
    asm volatile("tcgen05.alloc.cta_group::2.sync.aligned.shared::cta.b32 [%0], %1;" \
                 :: "r"((uint32_t)(sa)), "r"((uint32_t)(n)) : "memory")
#define TCGEN05_DEALLOC_CG2(tm, n) \
    asm volatile("tcgen05.dealloc.cta_group::2.sync.aligned.b32 %0, %1;" \
                 :: "r"(tm), "r"((uint32_t)(n)))
#define TCGEN05_RELINQ_CG2() \
    asm volatile("tcgen05.relinquish_alloc_permit.cta_group::2.sync.aligned;")
#define TCGEN05_COMMIT_MC_CG2(mbar, mask) \
    asm volatile("tcgen05.commit.cta_group::2.mbarrier::arrive::one.shared::cluster.multicast::cluster.b64 [%0], %1;" \
                 :: "r"((uint32_t)(mbar)), "h"((uint16_t)(mask)) : "memory")
#define TCGEN05_FENCE_AFTER() \
    asm volatile("tcgen05.fence::after_thread_sync;" ::: "memory")
#define TCGEN05_FENCE_BEFORE() \
    asm volatile("tcgen05.fence::before_thread_sync;" ::: "memory")
#define TCGEN05_WAIT_LD() \
    asm volatile("tcgen05.wait::ld.sync.aligned;" ::: "memory")

#define TCGEN05_LD_X32(r, ta) \
    asm volatile( \
        "tcgen05.ld.sync.aligned.32x32b.x32.b32 " \
        "{%0, %1, %2, %3, %4, %5, %6, %7, " \
        " %8, %9, %10, %11, %12, %13, %14, %15, " \
        " %16, %17, %18, %19, %20, %21, %22, %23, " \
        " %24, %25, %26, %27, %28, %29, %30, %31}, [%32];" \
        : "=r"((r)[0]),  "=r"((r)[1]),  "=r"((r)[2]),  "=r"((r)[3]), \
          "=r"((r)[4]),  "=r"((r)[5]),  "=r"((r)[6]),  "=r"((r)[7]), \
          "=r"((r)[8]),  "=r"((r)[9]),  "=r"((r)[10]), "=r"((r)[11]), \
          "=r"((r)[12]), "=r"((r)[13]), "=r"((r)[14]), "=r"((r)[15]), \
          "=r"((r)[16]), "=r"((r)[17]), "=r"((r)[18]), "=r"((r)[19]), \
          "=r"((r)[20]), "=r"((r)[21]), "=r"((r)[22]), "=r"((r)[23]), \
          "=r"((r)[24]), "=r"((r)[25]), "=r"((r)[26]), "=r"((r)[27]), \
          "=r"((r)[28]), "=r"((r)[29]), "=r"((r)[30]), "=r"((r)[31]) \
        : "r"(ta))

__device__ __forceinline__ void mma_f16_ss_cg2(
    uint32_t d_tmem, u64 a_desc, u64 b_desc, uint32_t idesc, bool en)
{
    uint32_t e = en ? 1u : 0u;
    asm volatile(
        "{\n\t.reg .pred p;\n\t"
        "setp.ne.u32 p, %6, 0;\n\t"
        "tcgen05.mma.cta_group::2.kind::f16 [%0], %1, %2, %3, "
        "{%4, %4, %4, %4, %4, %4, %4, %4}, p;\n\t}"
        :: "r"(d_tmem), "l"(a_desc), "l"(b_desc), "r"(idesc),
           "r"(0u), "r"(0u), "r"(e)
        : "memory");
}

static constexpr u64 SMEM_DESC_SW128 =
    (u64(2) << 61) | (u64(1) << 46) | (u64(64) << 32) | (u64(1) << 16);
__device__ __forceinline__ u64 mk_desc(uint32_t a) {
    return SMEM_DESC_SW128 | ((u64)(a >> 4) & 0x3FFF);
}
#endif  // HAS_TCGEN05

// ============================================================================
// Kernel 1: split x into fp16 hi/lo
// ============================================================================
__global__ __launch_bounds__(256) void k_split_x(const float* __restrict__ xg)
{
    const float4* x4 = (const float4*)xg;
    uint32_t* ahi = (uint32_t*)g_Ahi;
    uint32_t* alo = (uint32_t*)g_Alo;
    int stride = gridDim.x * blockDim.x;
    for (int q = blockIdx.x * blockDim.x + threadIdx.x; q < 4194304; q += stride) {
        float4 v = x4[q];
        __half h0 = __float2half_rn(v.x);
        __half h1 = __float2half_rn(v.y);
        __half h2 = __float2half_rn(v.z);
        __half h3 = __float2half_rn(v.w);
        __half l0 = __float2half_rn(v.x - __half2float(h0));
        __half l1 = __float2half_rn(v.y - __half2float(h1));
        __half l2 = __float2half_rn(v.z - __half2float(h2));
        __half l3 = __float2half_rn(v.w - __half2float(h3));
        __half2 hh0 = {h0, h1}, hh1 = {h2, h3};
        __half2 ll0 = {l0, l1}, ll1 = {l2, l3};
        ahi[2 * q]     = *(uint32_t*)&hh0;
        ahi[2 * q + 1] = *(uint32_t*)&hh1;
        alo[2 * q]     = *(uint32_t*)&ll0;
        alo[2 * q + 1] = *(uint32_t*)&ll1;
    }
}

// ============================================================================
// Kernel 2: densify W^T (K-major [n][m]) into fp16
// ============================================================================
__global__ __launch_bounds__(256) void k_densify(const float* __restrict__ c0g,
                                                 const float* __restrict__ c1g,
                                                 const float* __restrict__ c2g)
{
    __shared__ float sE[2048];
    __shared__ float sc2[2048];
    const int tid = threadIdx.x;
    const int m1 = blockIdx.x >> 4;
    const int m2 = blockIdx.x & 15;
    const int n1 = tid >> 4, n2 = tid & 15;

    float c0r[8];
#pragma unroll
    for (int r1 = 0; r1 < 8; ++r1) c0r[r1] = c0g[m1 * 128 + n1 * 8 + r1];
#pragma unroll
    for (int r2 = 0; r2 < 8; ++r2) {
        float acc = 0.0f;
#pragma unroll
        for (int r1 = 0; r1 < 8; ++r1)
            acc += c0r[r1] * c1g[(r1 * 16 + m2) * 128 + n2 * 8 + r2];
        sE[tid * 8 + r2] = acc;
    }
    for (int i = tid; i < 2048; i += 256) sc2[i] = c2g[i];
    __syncthreads();

    float Er[8];
#pragma unroll
    for (int r2 = 0; r2 < 8; ++r2) Er[r2] = sE[tid * 8 + r2];

#pragma unroll 1
    for (int n3 = 0; n3 < 16; ++n3) {
        __half hv[16];
#pragma unroll
        for (int m3 = 0; m3 < 16; ++m3) {
            float w = 0.0f;
#pragma unroll
            for (int r2 = 0; r2 < 8; ++r2)
                w += Er[r2] * sc2[r2 * 256 + m3 * 16 + n3];
            hv[m3] = __float2half_rn(w);
        }
        const int n = n1 * 256 + n2 * 16 + n3;
        const size_t boff = (size_t)n * 4096 + m1 * 256 + m2 * 16;
        *(uint4*)(g_Bhi + boff)     = ((uint4*)hv)[0];
        *(uint4*)(g_Bhi + boff + 8) = ((uint4*)hv)[1];
    }
}

// ============================================================================
// Kernel 3: cg2 tcgen05 GEMM, 256x256 tiles, 2-term split-fp16, K=4096.
// KB=128 per kstep (two 64-col SW128 K-blocks), 2-stage pipeline.
// ============================================================================
static constexpr int KSTEPS = 32;
static constexpr uint32_t GIDESC =
    (1u << 4) | (32u << 17) | (16u << 24);   // F32 accum, F16 a/b, N=256, M=256

static constexpr int OFF_TMEM  = 0;
static constexpr int OFF_READY = 16;    // 2 x 8B
static constexpr int OFF_DONE  = 48;    // 2 x 8B
static constexpr int OFF_TILES = 1024;  // stage s at +s*98304: Ahi,Alo,Bhi (32KB each)
static constexpr int STAGE_BYTES = 3 * 32768;
static constexpr int GEMM_SMEM = 1024 + 2 * STAGE_BYTES;   // 197632 B

__global__ __launch_bounds__(256, 1) __cluster_dims__(2, 1, 1)
void k_gemm(const float* __restrict__ xg, const float* __restrict__ biasg,
            float* __restrict__ outg)
{
#ifdef HAS_TCGEN05
    extern __shared__ char smem[];
    const uint32_t sb = smem_u32(smem);
    const int tid = threadIdx.x;
    const int wid = tid >> 5;
    const int lane = tid & 31;
    const uint32_t rank = cta_rank();

    const int pair  = blockIdx.x >> 1;
    const int mtile = pair >> 4;
    const int ntile = pair & 15;
    const int m_base = mtile * 256 + (int)rank * 128;
    const int n_base = ntile * 256 + (int)rank * 128;

    if (tid == 0) {
#pragma unroll
        for (int s = 0; s < 2; ++s) {
            MBARRIER_INIT(sb + OFF_READY + s * 8, 2);
            MBARRIER_INIT(sb + OFF_DONE + s * 8, 1);
        }
    }
    if (wid == 0) TCGEN05_ALLOC_CG2(sb + OFF_TMEM, 256);
    __syncthreads();
    uint32_t tmem;
    asm volatile("ld.shared.b32 %0, [%1];" : "=r"(tmem) : "r"(sb + OFF_TMEM));

    asm volatile("barrier.cluster.arrive.aligned;" ::: "memory");
    asm volatile("barrier.cluster.wait.aligned;" ::: "memory");

    // ---------------- loader warps (1..7) ----------------
    if (wid > 0) {
        const int lt = tid - 32;   // 0..223
        auto issue = [&](int ks) {
            const int s = ks & 1;
            const uint32_t stage = sb + OFF_TILES + s * STAGE_BYTES;
            // 3 tiles x 128 rows x 256B (two 16KB SW128 K-blocks per tile)
            for (int c = lt; c < 6144; c += 224) {
                const int tile = c >> 11;          // 0 Ahi, 1 Alo, 2 Bhi
                const int idx  = c & 2047;
                const int row  = idx >> 4;
                const int c16  = idx & 15;
                const int kb   = c16 >> 3;         // K-block 0/1
                const int w8   = c16 & 7;
                const __half* src;
                if (tile == 0)      src = g_Ahi + (size_t)(m_base + row) * 4096;
                else if (tile == 1) src = g_Alo + (size_t)(m_base + row) * 4096;
                else                src = g_Bhi + (size_t)(n_base + row) * 4096;
                src += ks * 128 + kb * 64 + w8 * 8;
                const uint32_t dst = stage + tile * 32768 + kb * 16384
                                   + sw128(row * 128 + w8 * 16);
                cpasync16(dst, src);
            }
            cp_commit();
        };
        // prologue: fill both stages; arm ready[0]
        issue(0); issue(1);
        cp_wait1();                                     // group 0 landed
        FENCE_PROXY_ASYNC();
        asm volatile("bar.sync 1, 224;" ::: "memory");
        if (lt == 0) MBAR_ARRIVE_CLU(sb + OFF_READY, 0);

        for (int ks = 0; ks < KSTEPS; ++ks) {
            // arm ready[ks+1] as soon as its data lands (off MMA critical path)
            if (ks + 1 < KSTEPS) {
                cp_wait0();                             // group ks+1 landed
                FENCE_PROXY_ASYNC();
                asm volatile("bar.sync 1, 224;" ::: "memory");
                if (lt == 0)
                    MBAR_ARRIVE_CLU(sb + OFF_READY + ((ks + 1) & 1) * 8, 0);
            }
            // stage recycle: wait MMA(ks) done, then refill with kstep ks+2
            MBAR_WAIT_PAR_CLU(sb + OFF_DONE + (ks & 1) * 8, (uint32_t)((ks >> 1) & 1));
            if (ks + 2 < KSTEPS) issue(ks + 2);
        }
    }
    // ---------------- MMA warp (leader CTA warp 0) ----------------
    else if (rank == 0) {
        for (int ks = 0; ks < KSTEPS; ++ks) {
            const int s = ks & 1;
            const uint32_t par = (uint32_t)((ks >> 1) & 1);
            MBAR_WAIT_PAR_CLU(sb + OFF_READY + s * 8, par);
            if (elect_one()) {
                const uint32_t stage = sb + OFF_TILES + s * STAGE_BYTES;
                const u64 dAhi = mk_desc(stage);
                const u64 dAlo = mk_desc(stage + 32768);
                const u64 dB   = mk_desc(stage + 65536);
#pragma unroll
                for (int k = 0; k < 8; ++k) {   // Ahi * B
                    const u64 off = (u64)((k >> 2) * 1024 + (k & 3) * 2);
                    mma_f16_ss_cg2(tmem, dAhi + off, dB + off, GIDESC,
                                   !(ks == 0 && k == 0));
                }
#pragma unroll
                for (int k = 0; k < 8; ++k) {   // Alo * B
                    const u64 off = (u64)((k >> 2) * 1024 + (k & 3) * 2);
                    mma_f16_ss_cg2(tmem, dAlo + off, dB + off, GIDESC, true);
                }
                TCGEN05_COMMIT_MC_CG2(sb + OFF_DONE + s * 8, 0x3);
            }
        }
    }

    __syncthreads();
    TCGEN05_FENCE_AFTER();

    // ---------------- epilogue: 128 lanes x 256 fp32 cols + bias -------------
    {
        const int sp = wid & 3;
        const int ch = wid >> 2;
        const int m_global = mtile * 256 + (int)rank * 128 + sp * 32 + lane;
        float* orow = outg + (size_t)m_global * 4096 + ntile * 256 + ch * 128;
        const float* brow = biasg + ntile * 256 + ch * 128;
        uint32_t r[32];
#pragma unroll 1
        for (int cb = 0; cb < 4; ++cb) {
            TCGEN05_LD_X32(r, tmem + ch * 128 + cb * 32);
            TCGEN05_WAIT_LD();
#pragma unroll
            for (int c = 0; c < 32; c += 4) {
                float4 b4 = *(const float4*)(brow + cb * 32 + c);
                float4 v;
                v.x = __uint_as_float(r[c + 0]) + b4.x;
                v.y = __uint_as_float(r[c + 1]) + b4.y;
                v.z = __uint_as_float(r[c + 2]) + b4.z;
                v.w = __uint_as_float(r[c + 3]) + b4.w;
                *(float4*)(orow + cb * 32 + c) = v;
            }
        }
        TCGEN05_FENCE_BEFORE();
    }

    __syncthreads();
    if (wid == 0) {
        TCGEN05_RELINQ_CG2();
        TCGEN05_DEALLOC_CG2(tmem, 256);
    }
    asm volatile("barrier.cluster.arrive.aligned;" ::: "memory");
    asm volatile("barrier.cluster.wait.aligned;" ::: "memory");
#else
    // -------- fallback: correct SIMT GEMM (insurance for non-'a' JIT) --------
    const int T = blockIdx.x * 256 + threadIdx.x;
    const int n  = T & 4095;
    const int mg = T >> 12;
    const __half* bh = g_Bhi + (size_t)n * 4096;
    const float bv = biasg[n];
    for (int mi = 0; mi < 128; ++mi) {
        const int m = mg * 128 + mi;
        const float* xr = xg + (size_t)m * 4096;
        float acc = 0.0f;
        for (int k = 0; k < 4096; ++k)
            acc += xr[k] * __half2float(bh[k]);
        outg[(size_t)m * 4096 + n] = acc + bv;
    }
#endif
}

// ============================================================================
extern "C" void kernel_launch(void* const* d_in, const int* in_sizes, int n_in,
                              void* d_out, int out_size)
{
    const float* x    = (const float*)d_in[0];
    const float* c0   = (const float*)d_in[1];
    const float* c1   = (const float*)d_in[2];
    const float* c2   = (const float*)d_in[3];
    const float* bias = (const float*)d_in[4];
    float* out = (float*)d_out;

    k_split_x<<<2048, 256>>>(x);
    k_densify<<<256, 256>>>(c0, c1, c2);

    cudaFuncSetAttribute(k_gemm, cudaFuncAttributeMaxDynamicSharedMemorySize,
                         GEMM_SMEM);
    k_gemm<<<512, 256, GEMM_SMEM>>>(x, bias, out);
}